// round 15
// baseline (speedup 1.0000x reference)
#include <cuda_runtime.h>
#include <cuda_bf16.h>

// Inputs (metadata order):
//   d_in[0] : energy_readout            float32 [262144]
//   d_in[1] : atomic_numbers            int32   [8388608]
//   d_in[2] : atomic_subsystem_indices  int32   [8388608]  (sorted ascending)
//   d_in[3] : self_energies_tensor      float32 [100]
// Output: float32 [262144] = energy_readout + segment_sum(se[Z], seg_idx)

#define CHUNK 8           // atoms per thread (exactly one chunk per thread)
#define TPB 128

__global__ void init_out_kernel(const float* __restrict__ e,
                                float* __restrict__ out, int n4) {
    int i = blockIdx.x * blockDim.x + threadIdx.x;
    if (i < n4) {
        reinterpret_cast<float4*>(out)[i] =
            reinterpret_cast<const float4*>(e)[i];
    }
}

__global__ void __launch_bounds__(TPB, 12)
self_energy_segsum_kernel(const int* __restrict__ zs,
                          const int* __restrict__ seg,
                          const float* __restrict__ se,
                          float* __restrict__ out,
                          int n_atoms) {
    long long base = (long long)(blockIdx.x * blockDim.x + threadIdx.x) * CHUNK;
    if (base >= n_atoms) return;

    if (base + CHUNK <= n_atoms) {
        const int4* z4 = reinterpret_cast<const int4*>(zs + base);
        const int4* s4 = reinterpret_cast<const int4*>(seg + base);

        int4 zv0 = z4[0], zv1 = z4[1];   // front-batched (MLP=4)
        int4 sv0 = s4[0], sv1 = s4[1];

        // LUT gathers from L1-resident 400B table (no smem prologue).
        float e0 = __ldg(se + zv0.x), e1 = __ldg(se + zv0.y);
        float e2 = __ldg(se + zv0.z), e3 = __ldg(se + zv0.w);
        float e4 = __ldg(se + zv1.x), e5 = __ldg(se + zv1.y);
        float e6 = __ldg(se + zv1.z), e7 = __ldg(se + zv1.w);

        int s0 = sv0.x, s1 = sv0.y, s2 = sv0.z, s3 = sv0.w;
        int s4_ = sv1.x, s5 = sv1.y, s6 = sv1.z, s7 = sv1.w;

        // Prefix-uniform flags: u_k = (s0..sk all equal). Pure ALU.
        bool u1 = (s1 == s0);
        bool u2 = u1 && (s2 == s1);
        bool u3 = u2 && (s3 == s2);
        bool u4 = u3 && (s4_ == s3);
        bool u5 = u4 && (s5 == s4_);
        bool u6 = u5 && (s6 == s5);
        bool u7 = u6 && (s7 == s6);

        // Suffix-uniform flags: v_k = (sk..s7 all equal).
        bool v6 = (s6 == s7);
        bool v5 = v6 && (s5 == s6);
        bool v4 = v5 && (s4_ == s5);
        bool v3 = v4 && (s3 == s4_);
        bool v2 = v3 && (s2 == s3);
        bool v1 = v2 && (s1 == s2);
        bool v0 = v1 && (s0 == s1);

        // First-run sum (equals whole-chunk sum when uniform): select-accumulate.
        float a1 = u1 ? e1 : 0.0f, a2 = u2 ? e2 : 0.0f, a3 = u3 ? e3 : 0.0f;
        float a4 = u4 ? e4 : 0.0f, a5 = u5 ? e5 : 0.0f, a6 = u6 ? e6 : 0.0f;
        float a7 = u7 ? e7 : 0.0f;
        float val0 = ((e0 + a1) + (a2 + a3)) + ((a4 + a5) + (a6 + a7));

        // Trailing-run sum; zeroed when chunk is uniform (avoid double count).
        float b0 = v0 ? e0 : 0.0f, b1 = v1 ? e1 : 0.0f, b2 = v2 ? e2 : 0.0f;
        float b3 = v3 ? e3 : 0.0f, b4 = v4 ? e4 : 0.0f, b5 = v5 ? e5 : 0.0f;
        float b6 = v6 ? e6 : 0.0f;
        float trail = ((b0 + b1) + (b2 + b3)) + ((b4 + b5) + (b6 + e7));
        float val7 = (s0 == s7) ? 0.0f : trail;

        // Two unconditional REDs (no branches in the common path).
        atomicAdd(out + s0, val0);
        atomicAdd(out + s7, val7);

        // Middle runs exist iff some position is past the first boundary AND
        // before the last boundary: !u_k && !v_k. With >=8-atom molecules this
        // is ~never true; keep exact handling for correctness.
        bool mid = (!u1 && !v1) || (!u2 && !v2) || (!u3 && !v3) ||
                   (!u4 && !v4) || (!u5 && !v5) || (!u6 && !v6);
        if (mid) {
            int   s[8] = {s0, s1, s2, s3, s4_, s5, s6, s7};
            float e[8] = {e0, e1, e2, e3, e4, e5, e6, e7};
            bool  uu[8] = {true, u1, u2, u3, u4, u5, u6, u7};
            bool  vv[8] = {v0, v1, v2, v3, v4, v5, v6, true};
            // Sum runs composed of positions that are neither in the first
            // run (u) nor the trailing run (v).
            int cs = -1; float rs = 0.0f;
#pragma unroll
            for (int k = 0; k < 8; k++) {
                if (!uu[k] && !vv[k]) {
                    if (s[k] != cs) {
                        if (cs >= 0) atomicAdd(out + cs, rs);
                        cs = s[k]; rs = 0.0f;
                    }
                    rs += e[k];
                }
            }
            if (cs >= 0) atomicAdd(out + cs, rs);
        }
    } else {
        // Tail safety (not hit for 8388608 atoms, but be general)
        int cs = -1; float rs = 0.0f;
        for (long long i = base; i < n_atoms; i++) {
            int s = seg[i];
            if (s != cs) { if (cs >= 0) atomicAdd(out + cs, rs); cs = s; rs = 0.0f; }
            rs += __ldg(se + zs[i]);
        }
        if (cs >= 0) atomicAdd(out + cs, rs);
    }
}

extern "C" void kernel_launch(void* const* d_in, const int* in_sizes, int n_in,
                              void* d_out, int out_size) {
    const float* energy = (const float*)d_in[0];
    const int*   zs     = (const int*)d_in[1];
    const int*   seg    = (const int*)d_in[2];
    const float* se     = (const float*)d_in[3];
    float* out = (float*)d_out;

    int n_mol   = in_sizes[0];
    int n_atoms = in_sizes[1];

    // 1) out = energy_readout (d_out comes in poisoned). n_mol is 4-aligned.
    {
        int n4 = n_mol / 4;
        int blocks = (n4 + TPB - 1) / TPB;
        init_out_kernel<<<blocks, TPB>>>(energy, out, n4);
    }

    // 2) branch-free segment sum: select-accumulate runs + 2 REDs per chunk
    {
        long long threads_needed = ((long long)n_atoms + CHUNK - 1) / CHUNK;
        int blocks = (int)((threads_needed + TPB - 1) / TPB);
        self_energy_segsum_kernel<<<blocks, TPB>>>(zs, seg, se, out, n_atoms);
    }
}